// round 13
// baseline (speedup 1.0000x reference)
#include <cuda_runtime.h>

#define BATCH   4
#define SEQ     2048
#define DIM     512
#define HEADS   8
#define DHEAD   64
#define INNER   512           // HEADS * DHEAD
#define QKV_W   (3 * INNER)   // 1536
#define SCALE_F 0.125f        // 64^-0.5

// Scratch (no allocations allowed)
__device__ float g_qkv[(size_t)BATCH * SEQ * QKV_W];   // 12.58M floats
__device__ float g_attn[(size_t)BATCH * SEQ * INNER];  // 4.19M floats
__device__ float g_wqkv_t[(size_t)QKV_W * DIM];        // w_qkv^T, tf32-hi
__device__ float g_wout_hi[(size_t)DIM * INNER];       // w_out^T, tf32-hi
__device__ float g_wout_lo[(size_t)DIM * INNER];       // w_out^T, tf32 residual

__device__ __forceinline__ unsigned f2tf32(float x) {
    unsigned r;
    asm("cvt.rna.tf32.f32 %0, %1;" : "=r"(r) : "f"(x));
    return r;
}

__device__ __forceinline__ void mma_tf32(
    float& c0, float& c1, float& c2, float& c3,
    unsigned a0, unsigned a1, unsigned a2, unsigned a3,
    unsigned b0, unsigned b1)
{
    asm volatile(
        "mma.sync.aligned.m16n8k8.row.col.f32.tf32.tf32.f32 "
        "{%0,%1,%2,%3}, {%4,%5,%6,%7}, {%8,%9}, {%0,%1,%2,%3};"
        : "+f"(c0), "+f"(c1), "+f"(c2), "+f"(c3)
        : "r"(a0), "r"(a1), "r"(a2), "r"(a3), "r"(b0), "r"(b1));
}

__device__ __forceinline__ void ldmx4(
    unsigned& r0, unsigned& r1, unsigned& r2, unsigned& r3, const void* p)
{
    unsigned addr = (unsigned)__cvta_generic_to_shared(p);
    asm volatile(
        "ldmatrix.sync.aligned.m8n8.x4.shared.b16 {%0,%1,%2,%3}, [%4];"
        : "=r"(r0), "=r"(r1), "=r"(r2), "=r"(r3) : "r"(addr));
}

__device__ __forceinline__ void ldmx2(
    unsigned& r0, unsigned& r1, const void* p)
{
    unsigned addr = (unsigned)__cvta_generic_to_shared(p);
    asm volatile(
        "ldmatrix.sync.aligned.m8n8.x2.shared.b16 {%0,%1}, [%2];"
        : "=r"(r0), "=r"(r1) : "r"(addr));
}

__device__ __forceinline__ void cp16(void* smem_dst, const void* gmem_src) {
    unsigned d = (unsigned)__cvta_generic_to_shared(smem_dst);
    asm volatile("cp.async.cg.shared.global [%0], [%1], 16;"
                 :: "r"(d), "l"(gmem_src));
}

// ---------------------------------------------------------------------------
// Weight transpose + tf32 pre-round: w[K][N] -> wt[N][K] (hi, and lo if mode 1)
// mode 0: w_qkv -> g_wqkv_t (hi only); mode 1: w_out -> g_wout_hi + g_wout_lo
// ---------------------------------------------------------------------------
__global__ void wtrans_kernel(const float* __restrict__ w, int K, int N, int mode)
{
    __shared__ float t[32][33];
    const int n0 = blockIdx.x * 32, k0 = blockIdx.y * 32;
    const int tx = threadIdx.x, ty = threadIdx.y;   // 32 x 8
    #pragma unroll
    for (int r = 0; r < 4; r++)
        t[ty + 8 * r][tx] = w[(size_t)(k0 + ty + 8 * r) * N + n0 + tx];
    __syncthreads();
    float* hi = (mode == 0) ? g_wqkv_t : g_wout_hi;
    float* lo = (mode == 0) ? nullptr  : g_wout_lo;
    #pragma unroll
    for (int r = 0; r < 4; r++) {
        float v = t[tx][ty + 8 * r];
        unsigned h = f2tf32(v);
        size_t idx = (size_t)(n0 + ty + 8 * r) * K + k0 + tx;
        hi[idx] = __uint_as_float(h);
        if (lo) lo[idx] = __uint_as_float(f2tf32(v - __uint_as_float(h)));
    }
}

// ---------------------------------------------------------------------------
// TF32 GEMM v2: cp.async double-buffered smem, all fragments via ldmatrix.
// C[M,N] = A[M,K] @ W[K,N] (+bias), with W pre-transposed/rounded in scratch.
// As[m][k], Bs[n][k], stride BK+4 (bank-conflict-free for ldmatrix).
// 128x128 tile, 8 warps (4x2), warp tile 32x64.
// mode 1: C=g_qkv, B=g_wqkv_t ; mode 2: A=g_attn, B=g_wout_hi(+lo, SPLIT)
// ---------------------------------------------------------------------------
template <int BK, bool SPLIT>
__global__ __launch_bounds__(256, 2) void gemm2_kernel(
    int M, int N, int K,
    const float* __restrict__ A,
    const float* __restrict__ bias,
    float* __restrict__ C,
    int mode)
{
    const float* Bth;
    const float* Btl = nullptr;
    if (mode == 1) { C = g_qkv;  Bth = g_wqkv_t; }
    else           { A = g_attn; Bth = g_wout_hi; Btl = g_wout_lo; }

    constexpr int ST    = BK + 4;
    constexpr int TILEF = 128 * ST;
    __shared__ float As[2][TILEF];
    __shared__ float Bs[2][TILEF];
    __shared__ float Bl[SPLIT ? 2 : 1][SPLIT ? TILEF : 1];

    const int tid  = threadIdx.x;
    const int lane = tid & 31;
    const int warp = tid >> 5;
    const int g    = lane >> 2;
    const int q    = lane & 3;
    const int rl   = lane & 7;
    const int jj   = lane >> 3;
    const int wm   = (warp & 3) * 32;
    const int wn   = (warp >> 2) * 64;

    const float* Ag  = A   + (size_t)blockIdx.y * 128 * K;
    const float* Bg  = Bth + (size_t)blockIdx.x * 128 * K;
    const float* Blg = SPLIT ? Btl + (size_t)blockIdx.x * 128 * K : nullptr;

    constexpr int CH = (128 * BK / 4) / 256;   // float4 chunks per thread

    float acc[2][8][4] = {};

    auto stage = [&](int t, int buf) {
        const int koff = t * BK;
        #pragma unroll
        for (int i = 0; i < CH; i++) {
            int c   = tid + i * 256;
            int row = c / (BK / 4);
            int kc  = (c % (BK / 4)) * 4;
            cp16(&As[buf][row * ST + kc], Ag + (size_t)row * K + koff + kc);
            cp16(&Bs[buf][row * ST + kc], Bg + (size_t)row * K + koff + kc);
            if (SPLIT)
                cp16(&Bl[buf][row * ST + kc], Blg + (size_t)row * K + koff + kc);
        }
        asm volatile("cp.async.commit_group;");
    };

    const int T = K / BK;
    stage(0, 0);

    for (int t = 0; t < T; t++) {
        const int buf = t & 1;
        if (t + 1 < T) {
            stage(t + 1, buf ^ 1);
            asm volatile("cp.async.wait_group 1;");
        } else {
            asm volatile("cp.async.wait_group 0;");
        }
        __syncthreads();

        const float* sA  = As[buf];
        const float* sB  = Bs[buf];
        const float* sBl = SPLIT ? Bl[buf] : nullptr;

        // B fragments: one ldmatrix per ni covers the whole BK tile.
        unsigned bh[8][2 * (BK / 8)];
        unsigned blr[SPLIT ? 8 : 1][SPLIT ? 2 * (BK / 8) : 1];
        #pragma unroll
        for (int ni = 0; ni < 8; ni++) {
            const float* p = sB + (wn + ni * 8 + rl) * ST + 4 * jj;
            if constexpr (BK == 16)
                ldmx4(bh[ni][0], bh[ni][1], bh[ni][2], bh[ni][3], p);
            else
                ldmx2(bh[ni][0], bh[ni][1], p);
            if constexpr (SPLIT) {
                const float* pl = sBl + (wn + ni * 8 + rl) * ST + 4 * jj;
                if constexpr (BK == 16)
                    ldmx4(blr[ni][0], blr[ni][1], blr[ni][2], blr[ni][3], pl);
                else
                    ldmx2(blr[ni][0], blr[ni][1], pl);
            }
        }

        #pragma unroll
        for (int kk = 0; kk < BK / 8; kk++) {
            unsigned ah[2][4], al[2][4];
            #pragma unroll
            for (int mi = 0; mi < 2; mi++) {
                unsigned r0, r1, r2, r3;
                const float* p = sA +
                    (wm + mi * 16 + (jj & 1) * 8 + rl) * ST + kk * 8 + (jj >> 1) * 4;
                ldmx4(r0, r1, r2, r3, p);
                float f0 = __uint_as_float(r0), f1 = __uint_as_float(r1);
                float f2 = __uint_as_float(r2), f3 = __uint_as_float(r3);
                ah[mi][0] = f2tf32(f0); ah[mi][1] = f2tf32(f1);
                ah[mi][2] = f2tf32(f2); ah[mi][3] = f2tf32(f3);
                if constexpr (SPLIT) {
                    al[mi][0] = f2tf32(f0 - __uint_as_float(ah[mi][0]));
                    al[mi][1] = f2tf32(f1 - __uint_as_float(ah[mi][1]));
                    al[mi][2] = f2tf32(f2 - __uint_as_float(ah[mi][2]));
                    al[mi][3] = f2tf32(f3 - __uint_as_float(ah[mi][3]));
                }
            }
            #pragma unroll
            for (int mi = 0; mi < 2; mi++)
                #pragma unroll
                for (int ni = 0; ni < 8; ni++) {
                    mma_tf32(acc[mi][ni][0], acc[mi][ni][1],
                             acc[mi][ni][2], acc[mi][ni][3],
                             ah[mi][0], ah[mi][1], ah[mi][2], ah[mi][3],
                             bh[ni][kk * 2], bh[ni][kk * 2 + 1]);
                    if constexpr (SPLIT) {
                        mma_tf32(acc[mi][ni][0], acc[mi][ni][1],
                                 acc[mi][ni][2], acc[mi][ni][3],
                                 ah[mi][0], ah[mi][1], ah[mi][2], ah[mi][3],
                                 blr[ni][kk * 2], blr[ni][kk * 2 + 1]);
                        mma_tf32(acc[mi][ni][0], acc[mi][ni][1],
                                 acc[mi][ni][2], acc[mi][ni][3],
                                 al[mi][0], al[mi][1], al[mi][2], al[mi][3],
                                 bh[ni][kk * 2], bh[ni][kk * 2 + 1]);
                    }
                }
        }
        __syncthreads();
    }

    #pragma unroll
    for (int mi = 0; mi < 2; mi++) {
        int row0 = blockIdx.y * 128 + wm + mi * 16 + g;
        #pragma unroll
        for (int ni = 0; ni < 8; ni++) {
            int col = blockIdx.x * 128 + wn + ni * 8 + 2 * q;
            float b0 = 0.f, b1 = 0.f;
            if (bias) { b0 = bias[col]; b1 = bias[col + 1]; }
            float2 r0 = {acc[mi][ni][0] + b0, acc[mi][ni][1] + b1};
            float2 r1 = {acc[mi][ni][2] + b0, acc[mi][ni][3] + b1};
            *(float2*)(C + (size_t)row0 * N + col)       = r0;
            *(float2*)(C + (size_t)(row0 + 8) * N + col) = r1;
        }
    }
}

// ---------------------------------------------------------------------------
// FlashAttention-2, TF32 mma.sync.
// S-phase: K fragments via ldmatrix (Ks[key][d], stride 68).
// PV-phase: V staged TRANSPOSED Vt[d][key] (stride 68) so V B-fragments also
// come from ldmatrix.x4 (one per (n, k-pair), covering two k-steps).
// ---------------------------------------------------------------------------
#define BQ  128
#define BKV 64
#define KS_STRIDE 68
#define VT_STRIDE 68

__global__ __launch_bounds__(256) void attn_kernel()
{
    __shared__ float Ks[BKV * KS_STRIDE];     // [key][d]
    __shared__ float Vt[DHEAD * VT_STRIDE];   // [d][key]

    const int tid  = threadIdx.x;
    const int lane = tid & 31;
    const int warp = tid >> 5;
    const int g    = lane >> 2;
    const int q    = lane & 3;
    const int rl   = lane & 7;
    const int jj   = lane >> 3;

    const int qt = blockIdx.x;
    const int bh = blockIdx.y;
    const int b  = bh >> 3;
    const int h  = bh & 7;

    const float* base = g_qkv + (size_t)b * SEQ * QKV_W + h * DHEAD;
    const int n0 = qt * BQ;

    const int qrow0 = n0 + warp * 16 + g;
    const int qrow1 = qrow0 + 8;

    unsigned qa[8][4];
    #pragma unroll
    for (int t = 0; t < 8; t++) {
        int c = t * 8 + q;
        qa[t][0] = f2tf32(SCALE_F * base[(size_t)qrow0 * QKV_W + c]);
        qa[t][1] = f2tf32(SCALE_F * base[(size_t)qrow1 * QKV_W + c]);
        qa[t][2] = f2tf32(SCALE_F * base[(size_t)qrow0 * QKV_W + c + 4]);
        qa[t][3] = f2tf32(SCALE_F * base[(size_t)qrow1 * QKV_W + c + 4]);
    }

    const float* kldm = Ks + (size_t)rl * KS_STRIDE + 4 * jj;
    const float* vldm = Vt + (size_t)rl * VT_STRIDE + 4 * jj;

    float m0 = -1e30f, m1 = -1e30f;
    float l0 = 0.f,    l1 = 0.f;
    float o[8][4] = {};

    for (int kt = 0; kt < SEQ / BKV; kt++) {
        const int kn0 = kt * BKV;

        // K: [key][d], float4 coalesced, tf32-rounded.
        #pragma unroll
        for (int i = 0; i < 4; i++) {
            int f4  = tid + i * 256;
            int row = f4 >> 4;
            int c4  = (f4 & 15) << 2;
            float4 kv = *(const float4*)(base + INNER +
                          (size_t)(kn0 + row) * QKV_W + c4);
            float4 kq = {__uint_as_float(f2tf32(kv.x)), __uint_as_float(f2tf32(kv.y)),
                         __uint_as_float(f2tf32(kv.z)), __uint_as_float(f2tf32(kv.w))};
            *(float4*)&Ks[row * KS_STRIDE + c4] = kq;
        }
        // V: transposed store Vt[d][key]. Thread: fixed d, 4 keys per iter
        // (coalesced scalar LDG across lanes; STS.128 along key, conflict-free
        //  per 8-lane phase: banks 4d+const).
        {
            int d  = tid & 63;
            int kg = tid >> 6;
            #pragma unroll
            for (int i = 0; i < 4; i++) {
                int key = kg * 4 + i * 16;
                const float* vp = base + 2 * INNER +
                                  (size_t)(kn0 + key) * QKV_W + d;
                float4 vq = {
                    __uint_as_float(f2tf32(vp[0 * QKV_W])),
                    __uint_as_float(f2tf32(vp[1 * QKV_W])),
                    __uint_as_float(f2tf32(vp[2 * QKV_W])),
                    __uint_as_float(f2tf32(vp[3 * QKV_W]))};
                *(float4*)&Vt[d * VT_STRIDE + key] = vq;
            }
        }
        __syncthreads();

        // S = Q @ K^T
        float c[8][4] = {};
        #pragma unroll
        for (int k = 0; k < 8; k += 2) {
            #pragma unroll
            for (int n = 0; n < 8; n++) {
                unsigned b0, b1, b2, b3;
                ldmx4(b0, b1, b2, b3, kldm + (size_t)n * 8 * KS_STRIDE + k * 8);
                mma_tf32(c[n][0], c[n][1], c[n][2], c[n][3],
                         qa[k][0], qa[k][1], qa[k][2], qa[k][3], b0, b1);
                mma_tf32(c[n][0], c[n][1], c[n][2], c[n][3],
                         qa[k+1][0], qa[k+1][1], qa[k+1][2], qa[k+1][3], b2, b3);
            }
        }

        // Online softmax on C-fragment layout
        float tm0 = -1e30f, tm1 = -1e30f;
        #pragma unroll
        for (int n = 0; n < 8; n++) {
            tm0 = fmaxf(tm0, fmaxf(c[n][0], c[n][1]));
            tm1 = fmaxf(tm1, fmaxf(c[n][2], c[n][3]));
        }
        #pragma unroll
        for (int off = 1; off < 4; off <<= 1) {
            tm0 = fmaxf(tm0, __shfl_xor_sync(0xffffffffu, tm0, off));
            tm1 = fmaxf(tm1, __shfl_xor_sync(0xffffffffu, tm1, off));
        }
        float nm0 = fmaxf(m0, tm0);
        float nm1 = fmaxf(m1, tm1);
        float al0 = __expf(m0 - nm0);
        float al1 = __expf(m1 - nm1);
        m0 = nm0; m1 = nm1;

        float s0 = 0.f, s1 = 0.f;
        #pragma unroll
        for (int n = 0; n < 8; n++) {
            c[n][0] = __expf(c[n][0] - m0);
            c[n][1] = __expf(c[n][1] - m0);
            c[n][2] = __expf(c[n][2] - m1);
            c[n][3] = __expf(c[n][3] - m1);
            s0 += c[n][0] + c[n][1];
            s1 += c[n][2] + c[n][3];
        }
        #pragma unroll
        for (int off = 1; off < 4; off <<= 1) {
            s0 += __shfl_xor_sync(0xffffffffu, s0, off);
            s1 += __shfl_xor_sync(0xffffffffu, s1, off);
        }
        l0 = l0 * al0 + s0;
        l1 = l1 * al1 + s1;

        #pragma unroll
        for (int n = 0; n < 8; n++) {
            o[n][0] *= al0; o[n][1] *= al0;
            o[n][2] *= al1; o[n][3] *= al1;
        }

        // O += P @ V : P C-frag -> A-frag via quad shuffles; V via ldmatrix.x4
        #pragma unroll
        for (int kp = 0; kp < 4; kp++) {
            unsigned paE[4], paO[4];
            #pragma unroll
            for (int e = 0; e < 2; e++) {
                int k = 2 * kp + e;
                int src_lo = (lane & ~3) | (q >> 1);
                int src_hi = src_lo + 2;
                float y00 = __shfl_sync(0xffffffffu, c[k][0], src_lo);
                float y01 = __shfl_sync(0xffffffffu, c[k][1], src_lo);
                float y10 = __shfl_sync(0xffffffffu, c[k][2], src_lo);
                float y11 = __shfl_sync(0xffffffffu, c[k][3], src_lo);
                float y20 = __shfl_sync(0xffffffffu, c[k][0], src_hi);
                float y21 = __shfl_sync(0xffffffffu, c[k][1], src_hi);
                float y30 = __shfl_sync(0xffffffffu, c[k][2], src_hi);
                float y31 = __shfl_sync(0xffffffffu, c[k][3], src_hi);
                bool odd = (q & 1);
                unsigned* pa = e ? paO : paE;
                pa[0] = f2tf32(odd ? y01 : y00);
                pa[1] = f2tf32(odd ? y11 : y10);
                pa[2] = f2tf32(odd ? y21 : y20);
                pa[3] = f2tf32(odd ? y31 : y30);
            }
            #pragma unroll
            for (int n = 0; n < 8; n++) {
                unsigned v0, v1, v2, v3;
                ldmx4(v0, v1, v2, v3,
                      vldm + (size_t)n * 8 * VT_STRIDE + kp * 16);
                mma_tf32(o[n][0], o[n][1], o[n][2], o[n][3],
                         paE[0], paE[1], paE[2], paE[3], v0, v1);
                mma_tf32(o[n][0], o[n][1], o[n][2], o[n][3],
                         paO[0], paO[1], paO[2], paO[3], v2, v3);
            }
        }
        __syncthreads();
    }

    float inv0 = 1.f / l0;
    float inv1 = 1.f / l1;
    #pragma unroll
    for (int n = 0; n < 8; n++) {
        int col = h * DHEAD + n * 8 + 2 * q;
        float2 r0 = {o[n][0] * inv0, o[n][1] * inv0};
        float2 r1 = {o[n][2] * inv1, o[n][3] * inv1};
        *(float2*)(g_attn + (size_t)(b * SEQ + qrow0) * INNER + col) = r0;
        *(float2*)(g_attn + (size_t)(b * SEQ + qrow1) * INNER + col) = r1;
    }
}

// ---------------------------------------------------------------------------
extern "C" void kernel_launch(void* const* d_in, const int* in_sizes, int n_in,
                              void* d_out, int out_size)
{
    const float* x     = (const float*)d_in[0];   // [4,2048,512]
    const float* w_qkv = (const float*)d_in[1];   // [512,1536]
    const float* w_out = (const float*)d_in[2];   // [512,512]
    const float* b_out = (const float*)d_in[3];   // [512]
    float* out = (float*)d_out;                   // [4,2048,512]

    const int M = BATCH * SEQ;                    // 8192

    // 0) pre-transpose + tf32-round weights into scratch
    wtrans_kernel<<<dim3(QKV_W / 32, DIM / 32), dim3(32, 8)>>>(
        w_qkv, DIM, QKV_W, 0);
    wtrans_kernel<<<dim3(DIM / 32, INNER / 32), dim3(32, 8)>>>(
        w_out, INNER, DIM, 1);

    // 1) qkv = x @ w_qkv -> g_qkv  (BK=16, single-pass tf32)
    dim3 g1(QKV_W / 128, M / 128);                // (12, 64)
    gemm2_kernel<16, false><<<g1, 256>>>(M, QKV_W, DIM, x, nullptr,
                                         nullptr, 1);

    // 2) attention -> g_attn
    dim3 g2(SEQ / BQ, BATCH * HEADS);             // (16, 32)
    attn_kernel<<<g2, 256>>>();

    // 3) out = g_attn @ w_out + b_out  (BK=8, 3-mma split ~ fp32)
    dim3 g3(DIM / 128, M / 128);                  // (4, 64)
    gemm2_kernel<8, true><<<g3, 256>>>(M, DIM, INNER, nullptr, b_out,
                                       out, 2);
}